// round 13
// baseline (speedup 1.0000x reference)
#include <cuda_runtime.h>
#include <cstdint>

#define B_  64
#define T_  2048
#define IN_ 64
#define H_  256
#define BT  (B_*T_)

#define ALPHA  0.2f
#define OMA    0.8f   // 1 - alpha

// Scratch for P = I @ W_in^T + b, padded by 2 steps for branchless prefetch.
__device__ float g_P[((size_t)BT + 2) * H_];

typedef unsigned long long u64;

__device__ __forceinline__ void ffma2(u64 &acc, u64 a, u64 b) {
    asm("fma.rn.f32x2 %0, %1, %2, %0;" : "+l"(acc) : "l"(a), "l"(b));
}
__device__ __forceinline__ u64 fadd2(u64 a, u64 b) {
    u64 r;
    asm("add.rn.f32x2 %0, %1, %2;" : "=l"(r) : "l"(a), "l"(b));
    return r;
}
__device__ __forceinline__ float lo32(u64 v) { return __uint_as_float((unsigned)v); }
__device__ __forceinline__ float hi32(u64 v) { return __uint_as_float((unsigned)(v >> 32)); }

// tanh via MUFU EX2 + MUFU RCP. rel err ~1e-6, far inside the 1e-3 budget.
__device__ __forceinline__ float tanh_fast(float x) {
    x = fminf(fmaxf(x, -20.f), 20.f);
    float e = __expf(2.f * x);
    return __fdividef(e - 1.f, e + 1.f);
}

// ---------------------------------------------------------------------------
// Kernel 1: P[bt][h] = I[bt] @ W_in[h] + b[h]   (R9 version — measured 343us)
// ---------------------------------------------------------------------------
__global__ void __launch_bounds__(256) pre_kernel(const float* __restrict__ I,
                                                  const float* __restrict__ Win,
                                                  const float* __restrict__ bvec) {
    __shared__ ulonglong2 sI[16 * 16];  // 16 rows x 64 floats
    const int row0 = blockIdx.x * 16;
    const int tid  = threadIdx.x;

    {
        const ulonglong2* I16 = (const ulonglong2*)(I + (size_t)row0 * IN_);
        sI[tid] = I16[tid];
    }
    __syncthreads();

    const int h = tid;
    u64 w2[32];
    const u64* W2 = (const u64*)(Win + h * IN_);
#pragma unroll
    for (int j = 0; j < 32; j++) w2[j] = W2[j];
    const float bb = bvec[h];

#pragma unroll 4
    for (int r = 0; r < 16; r++) {
        u64 aA = 0ull, aB = 0ull;
        const ulonglong2* ir = &sI[r * 16];
#pragma unroll
        for (int j4 = 0; j4 < 16; j4++) {
            ulonglong2 iv = ir[j4];
            ffma2(aA, w2[2 * j4 + 0], iv.x);
            ffma2(aB, w2[2 * j4 + 1], iv.y);
        }
        float acc = (lo32(aA) + hi32(aA)) + (lo32(aB) + hi32(aB)) + bb;
        g_P[(size_t)(row0 + r) * H_ + h] = acc;
    }
}

// ---------------------------------------------------------------------------
// Kernel 2: persistent recurrence with NH=4 r-reuse.
// 64 CTAs (one per batch), 256 threads: tid = h_local*4 + kq,
//   h_local in [0,64), kq in [0,4).
// Thread owns 4 h-rows {h_local + 64*i} over k-range [kq*64, kq*64+64):
//   - k-cols [0,44) of the range in registers: wra/wrb[4*11] u64 (176 regs)
//   - k-cols [44,64) in SMEM: wsm[(i*5+c)*256 + tid] (80 KB, coalesced)
// Each r chunk (LDS.128, 4 distinct addrs/warp) feeds 8 ffma2 (4 rows x 2).
// kq-partials joined with intra-quad shfl_xor(1),(2); thread updates row i=kq.
// One __syncthreads per step; r double-buffered.
// ---------------------------------------------------------------------------
#define NRC_H 11   // float4-chunks per h-row in RF   (44 k-cols)
#define NSC_H 5    // float4-chunks per h-row in SMEM (20 k-cols)
#define RST   272  // r buffer stride in floats

__global__ void __launch_bounds__(256, 1) rec_kernel(const float* __restrict__ x0,
                                                     const float* __restrict__ Wrec,
                                                     float* __restrict__ out_u) {
    extern __shared__ float smem[];
    ulonglong2* wsm = (ulonglong2*)smem;                 // [20][256] = 80 KB
    float* rbuf = smem + 4 * NSC_H * 256 * 4;            // 2 x RST floats

    const int tid     = threadIdx.x;
    const int h_local = tid >> 2;
    const int kq      = tid & 3;
    const int b       = blockIdx.x;
    const int kbase   = kq * 64;

    // W register part: rows i, chunks c -> floats [kbase+4c .. kbase+4c+3]
    u64 wra[4 * NRC_H], wrb[4 * NRC_H];
#pragma unroll
    for (int i = 0; i < 4; i++) {
        const u64* Wr = (const u64*)(Wrec + (size_t)(h_local + 64 * i) * H_ + kbase);
#pragma unroll
        for (int c = 0; c < NRC_H; c++) {
            wra[i * NRC_H + c] = Wr[2 * c];
            wrb[i * NRC_H + c] = Wr[2 * c + 1];
        }
    }
    // W SMEM part: rows i, chunks c -> floats [kbase+44+4c ..]
#pragma unroll
    for (int i = 0; i < 4; i++) {
        const float4* Wr4 = (const float4*)(Wrec + (size_t)(h_local + 64 * i) * H_ + kbase);
#pragma unroll
        for (int c = 0; c < NSC_H; c++) {
            float4 v = Wr4[NRC_H + c];
            wsm[(i * NSC_H + c) * 256 + tid] = *(ulonglong2*)&v;
        }
    }

    // This thread updates h = h_local + 64*kq.
    const int h = h_local + 64 * kq;
    float u = x0[b * H_ + h];
    const float* Pb = g_P + (size_t)b * T_ * H_ + h;
    float* ub = out_u + (size_t)b * T_ * H_ + h;
    float pv0 = __ldg(Pb);
    float pv1 = __ldg(Pb + H_);
    __syncthreads();

    for (int t = 0; t < T_; t++) {
        const int p = t & 1;
        const float r = tanh_fast(u);
        rbuf[p * RST + h] = r;               // all 256 h covered, once each
        __syncthreads();

        const ulonglong2* r16 = (const ulonglong2*)(rbuf + p * RST + kbase);
        u64 acc[8];
#pragma unroll
        for (int i = 0; i < 8; i++) acc[i] = 0ull;

#pragma unroll
        for (int c = 0; c < NRC_H; c++) {
            ulonglong2 rr = r16[c];          // 4 distinct 16B addrs per warp
#pragma unroll
            for (int i = 0; i < 4; i++) {
                ffma2(acc[2 * i],     wra[i * NRC_H + c], rr.x);
                ffma2(acc[2 * i + 1], wrb[i * NRC_H + c], rr.y);
            }
        }
#pragma unroll
        for (int c = 0; c < NSC_H; c++) {
            ulonglong2 rr = r16[NRC_H + c];
#pragma unroll
            for (int i = 0; i < 4; i++) {
                ulonglong2 wv = wsm[(i * NSC_H + c) * 256 + tid];  // coalesced
                ffma2(acc[2 * i],     wv.x, rr.x);
                ffma2(acc[2 * i + 1], wv.y, rr.y);
            }
        }

        // Join k-quarters within the quad; thread keeps row i = kq.
        float s0, s1, s2, s3;
        {
            u64 t0 = fadd2(acc[0], acc[1]);
            u64 t1 = fadd2(acc[2], acc[3]);
            u64 t2 = fadd2(acc[4], acc[5]);
            u64 t3 = fadd2(acc[6], acc[7]);
            s0 = lo32(t0) + hi32(t0);
            s1 = lo32(t1) + hi32(t1);
            s2 = lo32(t2) + hi32(t2);
            s3 = lo32(t3) + hi32(t3);
        }
        s0 += __shfl_xor_sync(0xffffffffu, s0, 1);
        s1 += __shfl_xor_sync(0xffffffffu, s1, 1);
        s2 += __shfl_xor_sync(0xffffffffu, s2, 1);
        s3 += __shfl_xor_sync(0xffffffffu, s3, 1);
        s0 += __shfl_xor_sync(0xffffffffu, s0, 2);
        s1 += __shfl_xor_sync(0xffffffffu, s1, 2);
        s2 += __shfl_xor_sync(0xffffffffu, s2, 2);
        s3 += __shfl_xor_sync(0xffffffffu, s3, 2);

        const float sum = (kq == 0) ? s0 : (kq == 1) ? s1 : (kq == 2) ? s2 : s3;

        u = fmaf(OMA, u, ALPHA * (sum + pv0));
        ub[(size_t)t * H_] = u;

        pv0 = pv1;
        pv1 = __ldg(Pb + (size_t)(t + 2) * H_);      // padded: branchless
    }
}

// ---------------------------------------------------------------------------
// Kernel 3: y[bt][j] = u[bt] @ Wout[j] + bout[j].  Warp per row.
// ---------------------------------------------------------------------------
__global__ void __launch_bounds__(256) y_kernel(const float* __restrict__ u,
                                                const float* __restrict__ Wout,
                                                const float* __restrict__ bout,
                                                float* __restrict__ y) {
    const int warp = threadIdx.x >> 5;
    const int lane = threadIdx.x & 31;
    const size_t row = (size_t)blockIdx.x * 8 + warp;

    const float4* u4  = (const float4*)(u + row * H_);
    const float4* w04 = (const float4*)(Wout);
    const float4* w14 = (const float4*)(Wout + H_);

    float s0 = 0.f, s1 = 0.f;
#pragma unroll
    for (int j = 0; j < 2; j++) {
        int idx = j * 32 + lane;
        float4 a  = u4[idx];
        float4 w0 = w04[idx];
        float4 w1 = w14[idx];
        s0 += a.x * w0.x + a.y * w0.y + a.z * w0.z + a.w * w0.w;
        s1 += a.x * w1.x + a.y * w1.y + a.z * w1.z + a.w * w1.w;
    }
#pragma unroll
    for (int off = 16; off; off >>= 1) {
        s0 += __shfl_xor_sync(0xffffffffu, s0, off);
        s1 += __shfl_xor_sync(0xffffffffu, s1, off);
    }
    if (lane == 0) {
        y[row * 2 + 0] = s0 + bout[0];
        y[row * 2 + 1] = s1 + bout[1];
    }
}

// ---------------------------------------------------------------------------
// Launch. Inputs: x0, I, W_in, W_rec, b, Wout, bout.
// Output: [u (B*T*H) | y (B*T*2)] concatenated.
// ---------------------------------------------------------------------------
extern "C" void kernel_launch(void* const* d_in, const int* in_sizes, int n_in,
                              void* d_out, int out_size) {
    const float* x0   = (const float*)d_in[0];
    const float* I    = (const float*)d_in[1];
    const float* Win  = (const float*)d_in[2];
    const float* Wrec = (const float*)d_in[3];
    const float* bv   = (const float*)d_in[4];
    const float* Wout = (const float*)d_in[5];
    const float* bout = (const float*)d_in[6];

    float* out_u = (float*)d_out;
    float* out_y = out_u + (size_t)BT * H_;

    const int smem_bytes = 4 * NSC_H * 256 * 16 + 2 * RST * 4;  // 81920 + 2176
    cudaFuncSetAttribute(rec_kernel, cudaFuncAttributeMaxDynamicSharedMemorySize,
                         smem_bytes);

    pre_kernel<<<BT / 16, 256>>>(I, Win, bv);
    rec_kernel<<<B_, 256, smem_bytes>>>(x0, Wrec, out_u);
    y_kernel<<<BT / 8, 256>>>(out_u, Wout, bout, out_y);
}

// round 14
// speedup vs baseline: 1.4284x; 1.4284x over previous
#include <cuda_runtime.h>
#include <cstdint>

#define B_  64
#define T_  2048
#define IN_ 64
#define H_  256
#define BT  (B_*T_)

#define ALPHA  0.2f
#define OMA    0.8f   // 1 - alpha

// Scratch for P = I @ W_in^T + b, padded by 2 steps for branchless prefetch.
__device__ float g_P[((size_t)BT + 2) * H_];

typedef unsigned long long u64;

__device__ __forceinline__ void ffma2(u64 &acc, u64 a, u64 b) {
    asm("fma.rn.f32x2 %0, %1, %2, %0;" : "+l"(acc) : "l"(a), "l"(b));
}
__device__ __forceinline__ u64 fadd2(u64 a, u64 b) {
    u64 r;
    asm("add.rn.f32x2 %0, %1, %2;" : "=l"(r) : "l"(a), "l"(b));
    return r;
}
__device__ __forceinline__ float lo32(u64 v) { return __uint_as_float((unsigned)v); }
__device__ __forceinline__ float hi32(u64 v) { return __uint_as_float((unsigned)(v >> 32)); }

// tanh via MUFU EX2 + MUFU RCP. rel err ~1e-6, far inside the 1e-3 budget.
__device__ __forceinline__ float tanh_fast(float x) {
    x = fminf(fmaxf(x, -20.f), 20.f);
    float e = __expf(2.f * x);
    return __fdividef(e - 1.f, e + 1.f);
}

// ---------------------------------------------------------------------------
// Kernel 1: P[bt][h] = I[bt] @ W_in[h] + b[h]
// Two rows per pass, 4 accumulator chains (halves the dependency depth that
// capped issue at 15%). Same LDS/FMA instruction counts as the R9 version.
// ---------------------------------------------------------------------------
__global__ void __launch_bounds__(256) pre_kernel(const float* __restrict__ I,
                                                  const float* __restrict__ Win,
                                                  const float* __restrict__ bvec) {
    __shared__ ulonglong2 sI[16 * 16];  // 16 rows x 64 floats
    const int row0 = blockIdx.x * 16;
    const int tid  = threadIdx.x;

    {
        const ulonglong2* I16 = (const ulonglong2*)(I + (size_t)row0 * IN_);
        sI[tid] = I16[tid];
    }
    __syncthreads();

    const int h = tid;
    u64 w2[32];
    const u64* W2 = (const u64*)(Win + h * IN_);
#pragma unroll
    for (int j = 0; j < 32; j++) w2[j] = W2[j];
    const float bb = bvec[h];

#pragma unroll 2
    for (int rp = 0; rp < 8; rp++) {
        u64 a0 = 0ull, a1 = 0ull, a2 = 0ull, a3 = 0ull;   // 4 indep chains
        const ulonglong2* ir0 = &sI[(2 * rp)     * 16];
        const ulonglong2* ir1 = &sI[(2 * rp + 1) * 16];
#pragma unroll
        for (int j4 = 0; j4 < 16; j4++) {
            ulonglong2 iv0 = ir0[j4];
            ulonglong2 iv1 = ir1[j4];
            ffma2(a0, w2[2 * j4 + 0], iv0.x);
            ffma2(a1, w2[2 * j4 + 1], iv0.y);
            ffma2(a2, w2[2 * j4 + 0], iv1.x);
            ffma2(a3, w2[2 * j4 + 1], iv1.y);
        }
        u64 s0 = fadd2(a0, a1);
        u64 s1 = fadd2(a2, a3);
        g_P[(size_t)(row0 + 2 * rp)     * H_ + h] = lo32(s0) + hi32(s0) + bb;
        g_P[(size_t)(row0 + 2 * rp + 1) * H_ + h] = lo32(s1) + hi32(s1) + bb;
    }
}

// ---------------------------------------------------------------------------
// Kernel 2: persistent recurrence — proven R2 layout + warp-phase staggering.
// 64 CTAs (one per batch), 256 threads (one per h). W_rec row h:
//   k[0,192) in registers (96 u64 pairs; the spill-proven footprint),
//   k[192,256) in SMEM [chunk][h] (conflict-free LDS.128, 64 KB).
// Phase staggering: odd warps run the SMEM-W phase BEFORE the register phase
// (disjoint accumulators -> order legal), so at any instant about half the
// warps feed the LDS crossbar while half feed the FMA pipe, overlapping the
// two pipes instead of serializing 1024 wf + 512 FMA cycles.
// ---------------------------------------------------------------------------
#define NREG_C  48   // float4-chunks of W in registers  (192 k-cols)
#define NSM_C   16   // float4-chunks of W in SMEM       ( 64 k-cols)
#define RPAD    272  // r buffer stride in floats

__global__ void __launch_bounds__(256, 1) rec_kernel(const float* __restrict__ x0,
                                                     const float* __restrict__ Wrec,
                                                     float* __restrict__ out_u) {
    extern __shared__ float smem[];
    ulonglong2* wsm = (ulonglong2*)smem;                 // [16][256] = 64 KB
    float* rbuf = smem + NSM_C * H_ * 4;                 // 2 x RPAD floats

    const int b = blockIdx.x;
    const int h = threadIdx.x;
    const int oddwarp = (threadIdx.x >> 5) & 1;

    // SMEM part of W: float4 chunks 48..63 of row h -> wsm[c][h]
    const float4* Wrow4 = (const float4*)(Wrec + h * H_);
#pragma unroll
    for (int c = 0; c < NSM_C; c++) {
        float4 v = Wrow4[NREG_C + c];
        wsm[c * H_ + h] = *(ulonglong2*)&v;
    }

    // Register part of W: 96 u64 pairs, two accumulator chains.
    u64 wrA[NREG_C], wrB[NREG_C];
    const u64* Wrow2 = (const u64*)(Wrec + h * H_);
#pragma unroll
    for (int c = 0; c < NREG_C; c++) {
        wrA[c] = Wrow2[2 * c];
        wrB[c] = Wrow2[2 * c + 1];
    }

    float u = x0[b * H_ + h];
    const float* Pb = g_P + (size_t)b * T_ * H_ + h;
    float* ub = out_u + (size_t)b * T_ * H_ + h;

    float pv0 = __ldg(Pb);           // P[t]
    float pv1 = __ldg(Pb + H_);      // P[t+1]
    __syncthreads();

    for (int t = 0; t < T_; t++) {
        float r = tanh_fast(u);
        float* rb = rbuf + (t & 1) * RPAD;
        rb[h] = r;
        __syncthreads();

        const ulonglong2* r16 = (const ulonglong2*)rb;
        u64 aA = 0ull, aB = 0ull, aC = 0ull, aD = 0ull;

        if (oddwarp) {
            // SMEM-W phase first
#pragma unroll
            for (int c = 0; c < NSM_C; c++) {
                ulonglong2 rr = r16[NREG_C + c];     // broadcast
                ulonglong2 wv = wsm[c * H_ + h];     // coalesced
                ffma2(aC, wv.x, rr.x);
                ffma2(aD, wv.y, rr.y);
            }
#pragma unroll
            for (int c = 0; c < NREG_C; c++) {
                ulonglong2 rr = r16[c];              // broadcast
                ffma2(aA, wrA[c], rr.x);
                ffma2(aB, wrB[c], rr.y);
            }
        } else {
            // Register phase first
#pragma unroll
            for (int c = 0; c < NREG_C; c++) {
                ulonglong2 rr = r16[c];
                ffma2(aA, wrA[c], rr.x);
                ffma2(aB, wrB[c], rr.y);
            }
#pragma unroll
            for (int c = 0; c < NSM_C; c++) {
                ulonglong2 rr = r16[NREG_C + c];
                ulonglong2 wv = wsm[c * H_ + h];
                ffma2(aC, wv.x, rr.x);
                ffma2(aD, wv.y, rr.y);
            }
        }

        u64 s = fadd2(fadd2(aA, aB), fadd2(aC, aD));
        float drive = (lo32(s) + hi32(s)) + pv0;
        u = fmaf(OMA, u, ALPHA * drive);
        ub[(size_t)t * H_] = u;                  // coalesced store

        pv0 = pv1;
        pv1 = __ldg(Pb + (size_t)(t + 2) * H_);  // padded: branchless
    }
}

// ---------------------------------------------------------------------------
// Kernel 3: y[bt][j] = u[bt] @ Wout[j] + bout[j].  Warp per row.
// ---------------------------------------------------------------------------
__global__ void __launch_bounds__(256) y_kernel(const float* __restrict__ u,
                                                const float* __restrict__ Wout,
                                                const float* __restrict__ bout,
                                                float* __restrict__ y) {
    const int warp = threadIdx.x >> 5;
    const int lane = threadIdx.x & 31;
    const size_t row = (size_t)blockIdx.x * 8 + warp;

    const float4* u4  = (const float4*)(u + row * H_);
    const float4* w04 = (const float4*)(Wout);
    const float4* w14 = (const float4*)(Wout + H_);

    float s0 = 0.f, s1 = 0.f;
#pragma unroll
    for (int j = 0; j < 2; j++) {
        int idx = j * 32 + lane;
        float4 a  = u4[idx];
        float4 w0 = w04[idx];
        float4 w1 = w14[idx];
        s0 += a.x * w0.x + a.y * w0.y + a.z * w0.z + a.w * w0.w;
        s1 += a.x * w1.x + a.y * w1.y + a.z * w1.z + a.w * w1.w;
    }
#pragma unroll
    for (int off = 16; off; off >>= 1) {
        s0 += __shfl_xor_sync(0xffffffffu, s0, off);
        s1 += __shfl_xor_sync(0xffffffffu, s1, off);
    }
    if (lane == 0) {
        y[row * 2 + 0] = s0 + bout[0];
        y[row * 2 + 1] = s1 + bout[1];
    }
}

// ---------------------------------------------------------------------------
// Launch. Inputs: x0, I, W_in, W_rec, b, Wout, bout.
// Output: [u (B*T*H) | y (B*T*2)] concatenated.
// ---------------------------------------------------------------------------
extern "C" void kernel_launch(void* const* d_in, const int* in_sizes, int n_in,
                              void* d_out, int out_size) {
    const float* x0   = (const float*)d_in[0];
    const float* I    = (const float*)d_in[1];
    const float* Win  = (const float*)d_in[2];
    const float* Wrec = (const float*)d_in[3];
    const float* bv   = (const float*)d_in[4];
    const float* Wout = (const float*)d_in[5];
    const float* bout = (const float*)d_in[6];

    float* out_u = (float*)d_out;
    float* out_y = out_u + (size_t)BT * H_;

    const int smem_bytes = NSM_C * H_ * 16 + 2 * RPAD * 4;   // 65536 + 2176
    cudaFuncSetAttribute(rec_kernel, cudaFuncAttributeMaxDynamicSharedMemorySize,
                         smem_bytes);

    pre_kernel<<<BT / 16, 256>>>(I, Win, bv);
    rec_kernel<<<B_, 256, smem_bytes>>>(x0, Wrec, out_u);
    y_kernel<<<BT / 8, 256>>>(out_u, Wout, bout, out_y);
}

// round 15
// speedup vs baseline: 2.1616x; 1.5133x over previous
#include <cuda_runtime.h>
#include <cstdint>

#define B_  64
#define T_  2048
#define IN_ 64
#define H_  256
#define BT  (B_*T_)

#define ALPHA  0.2f
#define OMA    0.8f   // 1 - alpha

// Scratch for P = I @ W_in^T + b (padded by 2 steps; harmless).
__device__ float g_P[((size_t)BT + 2) * H_];

typedef unsigned long long u64;

__device__ __forceinline__ void ffma2(u64 &acc, u64 a, u64 b) {
    asm("fma.rn.f32x2 %0, %1, %2, %0;" : "+l"(acc) : "l"(a), "l"(b));
}
__device__ __forceinline__ float lo32(u64 v) { return __uint_as_float((unsigned)v); }
__device__ __forceinline__ float hi32(u64 v) { return __uint_as_float((unsigned)(v >> 32)); }

// Accurate tanh via MUFU-backed __expf (rel err ~2 ulp) — the R1 version that
// produced the best measured rec_kernel.
__device__ __forceinline__ float tanh_acc(float x) {
    x = fminf(fmaxf(x, -30.f), 30.f);
    float e = __expf(2.f * x);
    return (e - 1.f) / (e + 1.f);
}

// ---------------------------------------------------------------------------
// Kernel 1: P[bt][h] = sum_k I[bt][k] * W_in[h][k] + b[h]
// LDS-byte-halved version of the measured-best scalar pre:
// block = 128 threads; thread owns TWO h-rows (tid, tid+128) with 32 float4
// of W in registers; each staged I chunk (LDS.128 broadcast) feeds 8 FMAs.
// Per block: 16 bt-rows, 32768 LDS-bytes streamed (was 65536 in R1).
// ---------------------------------------------------------------------------
__global__ void __launch_bounds__(128) pre_kernel(const float* __restrict__ I,
                                                  const float* __restrict__ Win,
                                                  const float* __restrict__ bvec) {
    __shared__ float4 sI[16 * 16];   // 16 rows x 64 floats
    const int row0 = blockIdx.x * 16;
    const int tid  = threadIdx.x;

    // cooperative stage of the 16 I rows (256 float4, two per thread, coalesced)
    const float4* I4 = (const float4*)(I + (size_t)row0 * IN_);
    sI[tid]       = I4[tid];
    sI[tid + 128] = I4[tid + 128];
    __syncthreads();

    const int h0 = tid;
    const int h1 = tid + 128;
    float4 w0[16], w1[16];
    const float4* W40 = (const float4*)(Win + h0 * IN_);
    const float4* W41 = (const float4*)(Win + h1 * IN_);
#pragma unroll
    for (int j = 0; j < 16; j++) { w0[j] = W40[j]; w1[j] = W41[j]; }
    const float bb0 = bvec[h0];
    const float bb1 = bvec[h1];

#pragma unroll 4
    for (int r = 0; r < 16; r++) {
        float acc0 = bb0, acc1 = bb1;
#pragma unroll
        for (int j = 0; j < 16; j++) {
            float4 iv = sI[r * 16 + j];   // broadcast, feeds BOTH h-rows
            acc0 += w0[j].x * iv.x + w0[j].y * iv.y + w0[j].z * iv.z + w0[j].w * iv.w;
            acc1 += w1[j].x * iv.x + w1[j].y * iv.y + w1[j].z * iv.z + w1[j].w * iv.w;
        }
        g_P[(size_t)(row0 + r) * H_ + h0] = acc0;   // coalesced over h
        g_P[(size_t)(row0 + r) * H_ + h1] = acc1;
    }
}

// ---------------------------------------------------------------------------
// Kernel 2: persistent recurrence — byte-exact restore of the R1 version
// (best measured: ~1796us). 64 CTAs (one per batch), 256 threads (one per h).
// W_rec row h: k[0,192) in registers (96 u64 pairs), k[192,256) in SMEM
// [j4][h] (conflict-free LDS.128). r broadcast via double-buffered SMEM,
// ONE __syncthreads per step.
// ---------------------------------------------------------------------------
__global__ void __launch_bounds__(256, 1) rec_kernel(const float* __restrict__ x0,
                                                     const float* __restrict__ Wrec,
                                                     float* __restrict__ out_u) {
    extern __shared__ float smem[];
    ulonglong2* wsm = (ulonglong2*)smem;          // [16][256] = 64 KB
    float* rbuf = smem + 16 * H_ * 4;             // 2 x 256 floats, 16B aligned

    const int b = blockIdx.x;
    const int h = threadIdx.x;

    // SMEM part of W: row h, float4 chunks 48..63  ->  wsm[j4][h]
    const float4* Wrow4 = (const float4*)(Wrec + h * H_);
#pragma unroll
    for (int j4 = 0; j4 < 16; j4++) {
        float4 v = Wrow4[48 + j4];
        wsm[j4 * H_ + h] = *(ulonglong2*)&v;
    }

    // Register part of W: 96 u64 = k pairs (0,1)..(190,191)
    u64 wr[96];
    const u64* Wrow2 = (const u64*)(Wrec + h * H_);
#pragma unroll
    for (int j = 0; j < 96; j++) wr[j] = Wrow2[j];

    float u = x0[b * H_ + h];
    const float* Pb = g_P + (size_t)b * T_ * H_;
    float* ub = out_u + (size_t)b * T_ * H_;

    float pv0 = __ldg(Pb + h);          // P[t]
    float pv1 = __ldg(Pb + H_ + h);     // P[t+1]
    __syncthreads();

    for (int t = 0; t < T_; t++) {
        float r = tanh_acc(u);
        float* rb = rbuf + (t & 1) * H_;
        rb[h] = r;
        __syncthreads();

        const ulonglong2* r16 = (const ulonglong2*)rb;
        u64 aA = 0ull, aB = 0ull;   // bit pattern {0.f, 0.f}
#pragma unroll
        for (int j4 = 0; j4 < 48; j4++) {
            ulonglong2 rr = r16[j4];            // LDS.128 broadcast
            ffma2(aA, wr[2 * j4],     rr.x);
            ffma2(aB, wr[2 * j4 + 1], rr.y);
        }
#pragma unroll
        for (int j4 = 0; j4 < 16; j4++) {
            ulonglong2 rr = r16[48 + j4];       // LDS.128 broadcast
            ulonglong2 wv = wsm[j4 * H_ + h];   // LDS.128 conflict-free
            ffma2(aA, wv.x, rr.x);
            ffma2(aB, wv.y, rr.y);
        }

        float drive = (lo32(aA) + hi32(aA)) + (lo32(aB) + hi32(aB)) + pv0;
        u = OMA * u + ALPHA * drive;
        ub[t * H_ + h] = u;                     // coalesced store

        pv0 = pv1;
        pv1 = (t + 2 < T_) ? __ldg(Pb + (size_t)(t + 2) * H_ + h) : 0.f;
    }
}

// ---------------------------------------------------------------------------
// Kernel 3: y[bt][j] = sum_h u[bt][h]*Wout[j][h] + bout[j].  Warp per row.
// ---------------------------------------------------------------------------
__global__ void __launch_bounds__(256) y_kernel(const float* __restrict__ u,
                                                const float* __restrict__ Wout,
                                                const float* __restrict__ bout,
                                                float* __restrict__ y) {
    const int warp = threadIdx.x >> 5;
    const int lane = threadIdx.x & 31;
    const size_t row = (size_t)blockIdx.x * 8 + warp;

    const float4* u4  = (const float4*)(u + row * H_);
    const float4* w04 = (const float4*)(Wout);
    const float4* w14 = (const float4*)(Wout + H_);

    float s0 = 0.f, s1 = 0.f;
#pragma unroll
    for (int j = 0; j < 2; j++) {
        int idx = j * 32 + lane;                // consecutive lanes -> coalesced
        float4 a  = u4[idx];
        float4 w0 = w04[idx];
        float4 w1 = w14[idx];
        s0 += a.x * w0.x + a.y * w0.y + a.z * w0.z + a.w * w0.w;
        s1 += a.x * w1.x + a.y * w1.y + a.z * w1.z + a.w * w1.w;
    }
#pragma unroll
    for (int off = 16; off; off >>= 1) {
        s0 += __shfl_xor_sync(0xffffffffu, s0, off);
        s1 += __shfl_xor_sync(0xffffffffu, s1, off);
    }
    if (lane == 0) {
        y[row * 2 + 0] = s0 + bout[0];
        y[row * 2 + 1] = s1 + bout[1];
    }
}

// ---------------------------------------------------------------------------
// Launch. Inputs (metadata order): x0, I, W_in, W_rec, b, Wout, bout.
// Output: [u (B*T*H) | y (B*T*2)] concatenated.
// ---------------------------------------------------------------------------
extern "C" void kernel_launch(void* const* d_in, const int* in_sizes, int n_in,
                              void* d_out, int out_size) {
    const float* x0   = (const float*)d_in[0];
    const float* I    = (const float*)d_in[1];
    const float* Win  = (const float*)d_in[2];
    const float* Wrec = (const float*)d_in[3];
    const float* bv   = (const float*)d_in[4];
    const float* Wout = (const float*)d_in[5];
    const float* bout = (const float*)d_in[6];

    float* out_u = (float*)d_out;
    float* out_y = out_u + (size_t)BT * H_;

    const int smem_bytes = (16 * H_ * 4 + 2 * H_) * (int)sizeof(float);  // 67584
    cudaFuncSetAttribute(rec_kernel, cudaFuncAttributeMaxDynamicSharedMemorySize,
                         smem_bytes);

    pre_kernel<<<BT / 16, 128>>>(I, Win, bv);
    rec_kernel<<<B_, 256, smem_bytes>>>(x0, Wrec, out_u);
    y_kernel<<<BT / 8, 256>>>(out_u, Wout, bout, out_y);
}